// round 2
// baseline (speedup 1.0000x reference)
#include <cuda_runtime.h>

#define BATCH      32768
#define DIM        1024
#define NUM_LAYERS 4
#define NUM_GATES  256   // DIM/4 float4 chunks per row
#define RPB        32    // rows per block

// Scratch for precomputed gate coefficients: [layer][gate][8]
// (u11r,u11i,u12r,u12i,u21r,u21i,u22r,u22i)
__device__ float g_coef[NUM_LAYERS * NUM_GATES * 8];

__global__ void precompute_coeffs_kernel(const float* __restrict__ W) {
    int idx = blockIdx.x * blockDim.x + threadIdx.x;  // 0..NUM_LAYERS*NUM_GATES-1
    if (idx >= NUM_LAYERS * NUM_GATES) return;
    const float* p = W + idx * 6;
    float a = p[0], b = p[1], c = p[2], d = p[3], e = p[4];
    float sa, ca, sb, cb, sc, cc, sd, cd, se, ce;
    sincosf(a, &sa, &ca);
    sincosf(b, &sb, &cb);
    sincosf(c, &sc, &cc);
    sincosf(d, &sd, &cd);
    sincosf(e, &se, &ce);
    float* o = g_coef + idx * 8;
    o[0] = ca * cb;  // u11.re
    o[1] = sa * cb;  // u11.im
    o[2] = cc * sb;  // u12.re
    o[3] = sc * sb;  // u12.im
    o[4] = cd * sb;  // u21.re
    o[5] = sd * sb;  // u21.im
    o[6] = ce * cb;  // u22.re
    o[7] = se * cb;  // u22.im
}

__global__ void __launch_bounds__(256)
apply_gates_kernel(const float4* __restrict__ x, float4* __restrict__ out) {
    const int g = threadIdx.x;              // gate / chunk index within row, 0..255
    const int row0 = blockIdx.x * RPB;

    // Load this gate's coefficients for all 4 layers into registers (2 float4 each)
    float4 cA[NUM_LAYERS], cB[NUM_LAYERS];
    const float4* cp = (const float4*)g_coef;
#pragma unroll
    for (int l = 0; l < NUM_LAYERS; l++) {
        cA[l] = __ldg(&cp[(l * NUM_GATES + g) * 2 + 0]);
        cB[l] = __ldg(&cp[(l * NUM_GATES + g) * 2 + 1]);
    }

    const float4* xin = x + (size_t)row0 * NUM_GATES + g;
    float4* xout = out + (size_t)row0 * NUM_GATES + g;

#pragma unroll 4
    for (int r = 0; r < RPB; r++) {
        float4 v = __ldcs(xin + (size_t)r * NUM_GATES);
#pragma unroll
        for (int l = 0; l < NUM_LAYERS; l++) {
            const float u11r = cA[l].x, u11i = cA[l].y;
            const float u12r = cA[l].z, u12i = cA[l].w;
            const float u21r = cB[l].x, u21i = cB[l].y;
            const float u22r = cB[l].z, u22i = cB[l].w;
            // (yi, yj) = U * (xi, xj), complex 2x2
            float yir = u11r * v.x - u11i * v.y + u12r * v.z - u12i * v.w;
            float yii = u11r * v.y + u11i * v.x + u12r * v.w + u12i * v.z;
            float yjr = u21r * v.x - u21i * v.y + u22r * v.z - u22i * v.w;
            float yji = u21r * v.y + u21i * v.x + u22r * v.w + u22i * v.z;
            v = make_float4(yir, yii, yjr, yji);
        }
        __stcs(xout + (size_t)r * NUM_GATES, v);
    }
}

extern "C" void kernel_launch(void* const* d_in, const int* in_sizes, int n_in,
                              void* d_out, int out_size) {
    const float* x = (const float*)d_in[0];   // (BATCH, DIM) fp32
    const float* W = (const float*)d_in[1];   // (NUM_LAYERS, NUM_GATES, 6) fp32
    float* out = (float*)d_out;               // (BATCH, DIM) fp32

    precompute_coeffs_kernel<<<4, 256>>>(W);
    apply_gates_kernel<<<BATCH / RPB, 256>>>((const float4*)x, (float4*)out);
}

// round 3
// speedup vs baseline: 1.2798x; 1.2798x over previous
#include <cuda_runtime.h>

#define BATCH      32768
#define DIM        1024
#define NUM_LAYERS 4
#define NUM_GATES  256   // DIM/4 float4 chunks per row
#define RPB        16    // rows per block

// Fused per-gate 2x2 complex matrix M = U4*U3*U2*U1, stored as
// [gate][8] = (m11r,m11i,m12r,m12i,m21r,m21i,m22r,m22i)
__device__ float g_coef[NUM_GATES * 8];

__global__ void precompute_coeffs_kernel(const float* __restrict__ W) {
    int g = blockIdx.x * blockDim.x + threadIdx.x;  // gate id
    if (g >= NUM_GATES) return;

    // M accumulates the product; init to identity
    float m11r = 1.f, m11i = 0.f, m12r = 0.f, m12i = 0.f;
    float m21r = 0.f, m21i = 0.f, m22r = 1.f, m22i = 0.f;

    for (int l = 0; l < NUM_LAYERS; l++) {
        const float* p = W + (l * NUM_GATES + g) * 6;
        float a = p[0], b = p[1], c = p[2], d = p[3], e = p[4];
        float sa, ca, sb, cb, sc, cc, sd, cd, se, ce;
        sincosf(a, &sa, &ca);
        sincosf(b, &sb, &cb);
        sincosf(c, &sc, &cc);
        sincosf(d, &sd, &cd);
        sincosf(e, &se, &ce);
        // layer matrix U
        float u11r = ca * cb, u11i = sa * cb;
        float u12r = cc * sb, u12i = sc * sb;
        float u21r = cd * sb, u21i = sd * sb;
        float u22r = ce * cb, u22i = se * cb;
        // M = U * M (complex 2x2 multiply)
        float n11r = u11r * m11r - u11i * m11i + u12r * m21r - u12i * m21i;
        float n11i = u11r * m11i + u11i * m11r + u12r * m21i + u12i * m21r;
        float n12r = u11r * m12r - u11i * m12i + u12r * m22r - u12i * m22i;
        float n12i = u11r * m12i + u11i * m12r + u12r * m22i + u12i * m22r;
        float n21r = u21r * m11r - u21i * m11i + u22r * m21r - u22i * m21i;
        float n21i = u21r * m11i + u21i * m11r + u22r * m21i + u22i * m21r;
        float n22r = u21r * m12r - u21i * m12i + u22r * m22r - u22i * m22i;
        float n22i = u21r * m12i + u21i * m12r + u22r * m22i + u22i * m22r;
        m11r = n11r; m11i = n11i; m12r = n12r; m12i = n12i;
        m21r = n21r; m21i = n21i; m22r = n22r; m22i = n22i;
    }

    float4* o = (float4*)(g_coef + g * 8);
    o[0] = make_float4(m11r, m11i, m12r, m12i);
    o[1] = make_float4(m21r, m21i, m22r, m22i);
}

__global__ void __launch_bounds__(256)
apply_gates_kernel(const float4* __restrict__ x, float4* __restrict__ out) {
    const int g = threadIdx.x;              // gate index within row, 0..255
    const int row0 = blockIdx.x * RPB;

    const float4* cp = (const float4*)g_coef;
    const float4 cA = __ldg(&cp[g * 2 + 0]);  // m11r,m11i,m12r,m12i
    const float4 cB = __ldg(&cp[g * 2 + 1]);  // m21r,m21i,m22r,m22i

    const float4* xin = x + (size_t)row0 * NUM_GATES + g;
    float4* xout = out + (size_t)row0 * NUM_GATES + g;

#pragma unroll 8
    for (int r = 0; r < RPB; r++) {
        float4 v = __ldcs(xin + (size_t)r * NUM_GATES);
        float yir = cA.x * v.x - cA.y * v.y + cA.z * v.z - cA.w * v.w;
        float yii = cA.x * v.y + cA.y * v.x + cA.z * v.w + cA.w * v.z;
        float yjr = cB.x * v.x - cB.y * v.y + cB.z * v.z - cB.w * v.w;
        float yji = cB.x * v.y + cB.y * v.x + cB.z * v.w + cB.w * v.z;
        __stcs(xout + (size_t)r * NUM_GATES, make_float4(yir, yii, yjr, yji));
    }
}

extern "C" void kernel_launch(void* const* d_in, const int* in_sizes, int n_in,
                              void* d_out, int out_size) {
    const float* x = (const float*)d_in[0];   // (BATCH, DIM) fp32
    const float* W = (const float*)d_in[1];   // (NUM_LAYERS, NUM_GATES, 6) fp32
    float* out = (float*)d_out;               // (BATCH, DIM) fp32

    precompute_coeffs_kernel<<<1, 256>>>(W);
    apply_gates_kernel<<<BATCH / RPB, 256>>>((const float4*)x, (float4*)out);
}